// round 5
// baseline (speedup 1.0000x reference)
#include <cuda_runtime.h>
#include <math.h>

#define W 512
#define H 512
#define HW (H * W)
#define TWO_PI 6.283185307179586f

#define NMAX 5000
#define TILE_W 16
#define TILE_H 8
#define TILES_X 32
#define NTILES 2048
#define CAP 128
#define NB 1184            // 148 SMs * 8 blocks, all co-resident (guaranteed by launch_bounds)

// Per-tile inlined gaussian records: 3 x float4 per entry.
//   q0 = (cx, cy, 0.5*A, 0.5*C)
//   q1 = (B, tmax, op*c0, op*c1)
//   q2 = (op*c2, -, -, -)
__device__ float4 g_tiledata[NTILES * CAP * 3];
__device__ int    g_tilecount[NTILES];   // zero-init BSS; render phase re-zeroes
__device__ int    g_arrive;              // grid barrier; reset by last finisher
__device__ int    g_done;

__global__ __launch_bounds__(128, 8) void fused_kernel(
        const float* __restrict__ xyz,
        const float* __restrict__ scaling,
        const float* __restrict__ rot,
        const float* __restrict__ feat,
        const float* __restrict__ opac,
        float* __restrict__ out,
        int n) {
    int tid = threadIdx.x;
    int bid = blockIdx.x;

    // ---------------- Phase 1: bin ----------------
    // gaussian g handled by block g % NB, thread g / NB  (n=5000 -> tids 0..4 active)
    for (int g = bid + tid * NB; g < n; g += NB * 128) {
        float2 xy = ((const float2*)xyz)[g];
        float2 sc = ((const float2*)scaling)[g];
        float mx = tanhf(xy.x);
        float my = tanhf(xy.y);
        float sx = fabsf(sc.x + 0.5f);
        float sy = fabsf(sc.y + 0.5f);
        float theta = (1.0f / (1.0f + expf(-rot[g]))) * TWO_PI;

        float cx = 0.5f * ((mx + 1.0f) * (float)W - 1.0f);
        float cy = 0.5f * ((my + 1.0f) * (float)H - 1.0f);

        float sth, cth;
        sincosf(theta, &sth, &cth);
        float sx2 = sx * sx;
        float sy2 = sy * sy;
        float a = cth * cth * sx2 + sth * sth * sy2;
        float b = cth * sth * (sx2 - sy2);
        float c = sth * sth * sx2 + cth * cth * sy2;
        float det = a * c - b * b;
        if (!(det > 0.0f)) continue;
        float inv_det = 1.0f / fmaxf(det, 1e-12f);
        float A = c * inv_det;
        float B = -b * inv_det;
        float C = a * inv_det;

        float op = opac[g];
        float tmax = logf(op * 255.0f);     // alpha > 1/255  <=>  sigma < tmax
        if (!(tmax > 0.0f)) continue;

        float rx = sqrtf(2.0f * tmax * a) + 1.0f;   // exact test re-rejects margin
        float ry = sqrtf(2.0f * tmax * c) + 1.0f;

        int x0 = max(0, (int)ceilf(cx - rx));
        int x1 = min(W - 1, (int)floorf(cx + rx));
        int y0 = max(0, (int)ceilf(cy - ry));
        int y1 = min(H - 1, (int)floorf(cy + ry));
        if (x1 < x0 || y1 < y0) continue;

        float4 q0 = make_float4(cx, cy, 0.5f * A, 0.5f * C);
        float4 q1 = make_float4(B, tmax, op * feat[3 * g], op * feat[3 * g + 1]);
        float4 q2 = make_float4(op * feat[3 * g + 2], 0.0f, 0.0f, 0.0f);

        int tx0 = x0 / TILE_W, tx1 = x1 / TILE_W;
        int ty0 = y0 / TILE_H, ty1 = y1 / TILE_H;
        for (int ty = ty0; ty <= ty1; ty++) {
            for (int tx = tx0; tx <= tx1; tx++) {
                int t = ty * TILES_X + tx;
                int s = atomicAdd(&g_tilecount[t], 1);
                if (s < CAP) {
                    float4* dst = &g_tiledata[(t * CAP + s) * 3];
                    dst[0] = q0;
                    dst[1] = q1;
                    dst[2] = q2;
                }
            }
        }
    }

    // ---------------- grid barrier ----------------
    __threadfence();
    __syncthreads();
    if (tid == 0) {
        atomicAdd(&g_arrive, 1);
        while (*((volatile int*)&g_arrive) < NB) { }
    }
    __syncthreads();
    __threadfence();

    // ---------------- Phase 2: render ----------------
    int lx = tid & 15;
    int ly = tid >> 4;
    for (int t = bid; t < NTILES; t += NB) {
        int px = ((t & (TILES_X - 1)) << 4) + lx;
        int py = ((t >> 5) << 3) + ly;
        float fx = (float)px;
        float fy = (float)py;

        int cnt = min(g_tilecount[t], CAP);
        __syncthreads();
        if (tid == 0) g_tilecount[t] = 0;    // reset for next graph replay

        const float4* __restrict__ td = &g_tiledata[t * CAP * 3];
        float acc0 = 0.0f, acc1 = 0.0f, acc2 = 0.0f;

        #pragma unroll 4
        for (int e = 0; e < cnt; e++) {
            float4 q0 = td[e * 3 + 0];   // cx, cy, hA, hC
            float4 q1 = td[e * 3 + 1];   // B, tmax, oc0, oc1
            float4 q2 = td[e * 3 + 2];   // oc2
            float dx = q0.x - fx;
            float dy = q0.y - fy;
            float sigma = fmaf(q0.z, dx * dx,
                          fmaf(q0.w, dy * dy, q1.x * (dx * dy)));
            float w = __expf(-sigma);
            w = ((sigma >= 0.0f) && (sigma < q1.y)) ? w : 0.0f;
            acc0 = fmaf(w, q1.z, acc0);
            acc1 = fmaf(w, q1.w, acc1);
            acc2 = fmaf(w, q2.x, acc2);
        }

        int pix = py * W + px;
        out[pix]          = fminf(fmaxf(acc0, 0.0f), 1.0f);
        out[HW + pix]     = fminf(fmaxf(acc1, 0.0f), 1.0f);
        out[2 * HW + pix] = fminf(fmaxf(acc2, 0.0f), 1.0f);
    }

    // ---------------- barrier-state reset for graph replay ----------------
    __syncthreads();
    if (tid == 0) {
        __threadfence();
        int d = atomicAdd(&g_done, 1);
        if (d == NB - 1) {               // last block out resets everything
            g_arrive = 0;
            g_done = 0;
            __threadfence();
        }
    }
}

extern "C" void kernel_launch(void* const* d_in, const int* in_sizes, int n_in,
                              void* d_out, int out_size) {
    const float* xyz     = (const float*)d_in[0];  // (N,2)
    const float* scaling = (const float*)d_in[1];  // (N,2)
    const float* rot     = (const float*)d_in[2];  // (N,1)
    const float* feat    = (const float*)d_in[3];  // (N,3)
    const float* opac    = (const float*)d_in[4];  // (N,1)
    float* out = (float*)d_out;                     // (1,3,512,512)

    int n = in_sizes[0] / 2;

    fused_kernel<<<NB, 128>>>(xyz, scaling, rot, feat, opac, out, n);
}

// round 6
// speedup vs baseline: 1.9870x; 1.9870x over previous
#include <cuda_runtime.h>
#include <math.h>

#define W 512
#define H 512
#define HW (H * W)
#define TWO_PI 6.283185307179586f
#define ALPHA_THRESH (1.0f / 255.0f)

// Interleaved accumulation plane: (c0, c1, c2, junk) per pixel.
// Zero-initialized BSS; finalize re-zeroes it every replay.
__device__ float4 g_accum[HW];

__global__ __launch_bounds__(256) void splat_kernel(
        const float* __restrict__ xyz,
        const float* __restrict__ scaling,
        const float* __restrict__ rot,
        const float* __restrict__ feat,
        const float* __restrict__ opac,
        int n) {
    int g = (blockIdx.x * blockDim.x + threadIdx.x) >> 5;
    int lane = threadIdx.x & 31;
    if (g >= n) return;

    // Per-gaussian prep (all lanes redundantly; loads broadcast via L1)
    float2 xy = ((const float2*)xyz)[g];
    float2 sc = ((const float2*)scaling)[g];
    float mx = tanhf(xy.x);
    float my = tanhf(xy.y);
    float sx = fabsf(sc.x + 0.5f);
    float sy = fabsf(sc.y + 0.5f);
    float theta = (1.0f / (1.0f + expf(-rot[g]))) * TWO_PI;

    float cx = 0.5f * ((mx + 1.0f) * (float)W - 1.0f);
    float cy = 0.5f * ((my + 1.0f) * (float)H - 1.0f);

    float sth, cth;
    sincosf(theta, &sth, &cth);
    float sx2 = sx * sx;
    float sy2 = sy * sy;
    float a = cth * cth * sx2 + sth * sth * sy2;
    float b = cth * sth * (sx2 - sy2);
    float c = sth * sth * sx2 + cth * cth * sy2;
    float det = a * c - b * b;
    if (!(det > 0.0f)) return;
    float inv_det = 1.0f / fmaxf(det, 1e-12f);
    float hA = 0.5f * c * inv_det;      // 0.5*A
    float B  = -b * inv_det;
    float hC = 0.5f * a * inv_det;      // 0.5*C

    float op = opac[g];
    float tmax = logf(op * 255.0f);     // alpha > 1/255  <=>  sigma < tmax
    if (!(tmax > 0.0f)) return;

    // bbox half-extents; a,c <= 2.25 and tmax <= ln(255*op) => rx,ry <= ~6.1
    float rx = sqrtf(2.0f * tmax * a) + 1.0f;
    float ry = sqrtf(2.0f * tmax * c) + 1.0f;

    int x0 = max(0, (int)ceilf(cx - rx));
    int x1 = min(W - 1, (int)floorf(cx + rx));
    int y0 = max(0, (int)ceilf(cy - ry));
    int y1 = min(H - 1, (int)floorf(cy + ry));
    if (x1 < x0 || y1 < y0) return;

    float c0 = op * feat[3 * g];
    float c1 = op * feat[3 * g + 1];
    float c2 = op * feat[3 * g + 2];

    // bbox width <= 13 <= 32: lane indexes x, warp loops rows.
    int px = x0 + lane;
    float dx = cx - (float)px;
    float sxx = hA * dx * dx;            // per-lane constant across rows
    float bdx = B * dx;
    bool xin = (px <= x1);

    for (int py = y0; py <= y1; py++) {
        float dy = cy - (float)py;
        float sigma = fmaf(hC, dy, bdx) * dy + sxx;   // hA*dx^2 + hC*dy^2 + B*dx*dy
        float w = __expf(-sigma);
        float alpha = op * w;
        if (xin && sigma >= 0.0f && alpha > ALPHA_THRESH) {
            float4* dst = &g_accum[py * W + px];
            asm volatile("red.global.add.v4.f32 [%0], {%1, %2, %3, %4};"
                         :: "l"(dst), "f"(w * (op * feat[3 * g])), "f"(w * c1),
                            "f"(w * c2), "f"(0.0f)
                         : "memory");
        }
    }
}

__global__ __launch_bounds__(256) void finalize_kernel(float* __restrict__ out) {
    int pix = blockIdx.x * blockDim.x + threadIdx.x;
    if (pix >= HW) return;
    float4 v = g_accum[pix];
    g_accum[pix] = make_float4(0.0f, 0.0f, 0.0f, 0.0f);   // re-arm for next replay
    out[pix]          = fminf(fmaxf(v.x, 0.0f), 1.0f);
    out[HW + pix]     = fminf(fmaxf(v.y, 0.0f), 1.0f);
    out[2 * HW + pix] = fminf(fmaxf(v.z, 0.0f), 1.0f);
}

extern "C" void kernel_launch(void* const* d_in, const int* in_sizes, int n_in,
                              void* d_out, int out_size) {
    const float* xyz     = (const float*)d_in[0];  // (N,2)
    const float* scaling = (const float*)d_in[1];  // (N,2)
    const float* rot     = (const float*)d_in[2];  // (N,1)
    const float* feat    = (const float*)d_in[3];  // (N,3)
    const float* opac    = (const float*)d_in[4];  // (N,1)
    float* out = (float*)d_out;                     // (1,3,512,512)

    int n = in_sizes[0] / 2;

    int warps_per_block = 8;                        // 256 threads
    int blocks = (n + warps_per_block - 1) / warps_per_block;
    splat_kernel<<<blocks, 256>>>(xyz, scaling, rot, feat, opac, n);
    finalize_kernel<<<HW / 256, 256>>>(out);
}

// round 7
// speedup vs baseline: 2.7463x; 1.3821x over previous
#include <cuda_runtime.h>
#include <math.h>

#define W 512
#define H 512
#define HW (H * W)          // 262144
#define QW (HW / 4)         // 65536
#define TWO_PI 6.283185307179586f
#define ALPHA_THRESH (1.0f / 255.0f)

// Interleaved accumulation plane: (c0, c1, c2, junk) per pixel.
// Zero-initialized BSS; finalize re-zeroes it every replay.
__device__ float4 g_accum[HW];

__global__ __launch_bounds__(256) void splat_kernel(
        const float* __restrict__ xyz,
        const float* __restrict__ scaling,
        const float* __restrict__ rot,
        const float* __restrict__ feat,
        const float* __restrict__ opac,
        int n) {
    int g = (blockIdx.x * blockDim.x + threadIdx.x) >> 5;
    int lane = threadIdx.x & 31;
    if (g >= n) return;

    // Per-gaussian prep (all lanes redundantly; loads broadcast via L1)
    float2 xy = ((const float2*)xyz)[g];
    float2 sc = ((const float2*)scaling)[g];
    float mx = tanhf(xy.x);
    float my = tanhf(xy.y);
    float sx = fabsf(sc.x + 0.5f);
    float sy = fabsf(sc.y + 0.5f);
    float theta = (1.0f / (1.0f + expf(-rot[g]))) * TWO_PI;

    float cx = 0.5f * ((mx + 1.0f) * (float)W - 1.0f);
    float cy = 0.5f * ((my + 1.0f) * (float)H - 1.0f);

    float sth, cth;
    sincosf(theta, &sth, &cth);
    float sx2 = sx * sx;
    float sy2 = sy * sy;
    float a = cth * cth * sx2 + sth * sth * sy2;
    float b = cth * sth * (sx2 - sy2);
    float c = sth * sth * sx2 + cth * cth * sy2;
    float det = a * c - b * b;
    if (!(det > 0.0f)) return;
    float inv_det = 1.0f / fmaxf(det, 1e-12f);
    float hA = 0.5f * c * inv_det;      // 0.5*A
    float B  = -b * inv_det;
    float hC = 0.5f * a * inv_det;      // 0.5*C

    float op = opac[g];
    float tmax = logf(op * 255.0f);     // alpha > 1/255  <=>  sigma < tmax
    if (!(tmax > 0.0f)) return;

    float rx = sqrtf(2.0f * tmax * a) + 1.0f;
    float ry = sqrtf(2.0f * tmax * c) + 1.0f;

    int x0 = max(0, (int)ceilf(cx - rx));
    int x1 = min(W - 1, (int)floorf(cx + rx));
    int y0 = max(0, (int)ceilf(cy - ry));
    int y1 = min(H - 1, (int)floorf(cy + ry));
    if (x1 < x0 || y1 < y0) return;

    float c0 = op * feat[3 * g];
    float c1 = op * feat[3 * g + 1];
    float c2 = op * feat[3 * g + 2];

    // bbox width <= 13 <= 32: lane indexes x, warp loops rows.
    int px = x0 + lane;
    float dx = cx - (float)px;
    float sxx = hA * dx * dx;            // per-lane constant across rows
    float bdx = B * dx;
    bool xin = (px <= x1);

    for (int py = y0; py <= y1; py++) {
        float dy = cy - (float)py;
        float sigma = fmaf(hC, dy, bdx) * dy + sxx;   // hA*dx^2 + hC*dy^2 + B*dx*dy
        float w = __expf(-sigma);
        float alpha = op * w;
        if (xin && sigma >= 0.0f && alpha > ALPHA_THRESH) {
            float4* dst = &g_accum[py * W + px];
            asm volatile("red.global.add.v4.f32 [%0], {%1, %2, %3, %4};"
                         :: "l"(dst), "f"(w * c0), "f"(w * c1),
                            "f"(w * c2), "f"(0.0f)
                         : "memory");
        }
    }
}

__global__ __launch_bounds__(256) void finalize_kernel(float* __restrict__ out) {
    int t = blockIdx.x * blockDim.x + threadIdx.x;   // 65536 threads, 4 px each

    // 4 independent loads up front -> MLP = 4 per thread
    float4 v0 = g_accum[t];
    float4 v1 = g_accum[t + QW];
    float4 v2 = g_accum[t + 2 * QW];
    float4 v3 = g_accum[t + 3 * QW];

    float4 z = make_float4(0.0f, 0.0f, 0.0f, 0.0f);
    g_accum[t]          = z;           // re-arm for next graph replay
    g_accum[t + QW]     = z;
    g_accum[t + 2 * QW] = z;
    g_accum[t + 3 * QW] = z;

    #define CLAMP(x) fminf(fmaxf((x), 0.0f), 1.0f)
    __stcs(&out[t],                    CLAMP(v0.x));
    __stcs(&out[t + QW],               CLAMP(v1.x));
    __stcs(&out[t + 2 * QW],           CLAMP(v2.x));
    __stcs(&out[t + 3 * QW],           CLAMP(v3.x));

    __stcs(&out[HW + t],               CLAMP(v0.y));
    __stcs(&out[HW + t + QW],          CLAMP(v1.y));
    __stcs(&out[HW + t + 2 * QW],      CLAMP(v2.y));
    __stcs(&out[HW + t + 3 * QW],      CLAMP(v3.y));

    __stcs(&out[2 * HW + t],           CLAMP(v0.z));
    __stcs(&out[2 * HW + t + QW],      CLAMP(v1.z));
    __stcs(&out[2 * HW + t + 2 * QW],  CLAMP(v2.z));
    __stcs(&out[2 * HW + t + 3 * QW],  CLAMP(v3.z));
    #undef CLAMP
}

extern "C" void kernel_launch(void* const* d_in, const int* in_sizes, int n_in,
                              void* d_out, int out_size) {
    const float* xyz     = (const float*)d_in[0];  // (N,2)
    const float* scaling = (const float*)d_in[1];  // (N,2)
    const float* rot     = (const float*)d_in[2];  // (N,1)
    const float* feat    = (const float*)d_in[3];  // (N,3)
    const float* opac    = (const float*)d_in[4];  // (N,1)
    float* out = (float*)d_out;                     // (1,3,512,512)

    int n = in_sizes[0] / 2;

    int blocks = (n + 7) / 8;                       // 8 warps/block, 1 gaussian/warp
    splat_kernel<<<blocks, 256>>>(xyz, scaling, rot, feat, opac, n);
    finalize_kernel<<<QW / 256, 256>>>(out);
}